// round 3
// baseline (speedup 1.0000x reference)
#include <cuda_runtime.h>
#include <math.h>

// ---------------- problem constants ----------------
constexpr int N_NODES = 10000;
constexpr int N_EDGES = 160000;
constexpr int B       = 8;
constexpr int T_IN    = 12;
constexpr int HP      = 64;
constexpr int HV      = 32;
constexpr int CDIM    = 2 * HP + 1;   // 129
constexpr int NB      = N_NODES * B;  // 80000
constexpr int EB      = N_EDGES * B;  // 1280000

// ---------------- device scratch (static; no allocation) ----------------
__device__ float4       g_node[NB];     // per (node,b): P, R, S, Q
__device__ float        g_att[EB];      // a, then reused as ex
__device__ float        g_dsum[EB];     // sum_k diff*feature[src]
__device__ unsigned int g_amax[NB];     // ordered-uint encoded float max
__device__ float        g_den[NB];      // softmax denominator
__device__ float        g_gw[CDIM];     // ln2_g * attn_w
__device__ float        g_GC[2];        // [0]=sum(g*w), [1]=sum(b*w)

// ---------------- helpers ----------------
__device__ __forceinline__ unsigned int f2ord(float f) {
    unsigned int u = __float_as_uint(f);
    return (u & 0x80000000u) ? ~u : (u | 0x80000000u);
}
__device__ __forceinline__ float ord2f(unsigned int u) {
    return (u & 0x80000000u) ? __uint_as_float(u & 0x7FFFFFFFu)
                             : __uint_as_float(~u);
}

// ---------------- prep: gw = ln2_g*attn_w; G = sum(gw); C = sum(ln2_b*attn_w) ----------------
__global__ void prep_kernel(const float* __restrict__ ln2g,
                            const float* __restrict__ ln2b,
                            const float* __restrict__ attnw) {
    __shared__ float sG[256];
    __shared__ float sC[256];
    int t = threadIdx.x;
    float gv = 0.f, cv = 0.f;
    if (t < CDIM) {
        float w = attnw[t];
        gv = ln2g[t] * w;
        cv = ln2b[t] * w;
        g_gw[t] = gv;
    }
    sG[t] = gv; sC[t] = cv;
    __syncthreads();
    for (int s = 128; s > 0; s >>= 1) {
        if (t < s) { sG[t] += sG[t + s]; sC[t] += sC[t + s]; }
        __syncthreads();
    }
    if (t == 0) { g_GC[0] = sG[0]; g_GC[1] = sC[0]; }
}

// ---------------- init: zero pred, den, amax ----------------
__global__ void init_kernel(float* __restrict__ out) {
    int t = blockIdx.x * blockDim.x + threadIdx.x;
    if (t < NB) {
        out[t]    = 0.f;
        g_den[t]  = 0.f;
        g_amax[t] = 0u;   // below ordered-encoding of any finite float
    }
}

// ---------------- node kernel: fold z into (P,R,S,Q) ----------------
__global__ __launch_bounds__(128)
void node_kernel(const float* __restrict__ feat,
                 const float* __restrict__ fcw) {
    __shared__ float sw[HP * T_IN];   // 768
    __shared__ float sgw[2 * HP];     // 128
    int tid = threadIdx.x;
    for (int i = tid; i < HP * T_IN; i += blockDim.x) sw[i]  = fcw[i];
    for (int i = tid; i < 2 * HP;    i += blockDim.x) sgw[i] = g_gw[i];
    __syncthreads();

    int t = blockIdx.x * blockDim.x + tid;
    if (t >= NB) return;

    float fr[T_IN];
    {
        const float4* f4 = reinterpret_cast<const float4*>(feat) + (size_t)t * 3;
        float4 a0 = f4[0], a1 = f4[1], a2 = f4[2];
        fr[0]=a0.x; fr[1]=a0.y; fr[2]=a0.z;  fr[3]=a0.w;
        fr[4]=a1.x; fr[5]=a1.y; fr[6]=a1.z;  fr[7]=a1.w;
        fr[8]=a2.x; fr[9]=a2.y; fr[10]=a2.z; fr[11]=a2.w;
    }

    float P = 0.f, R = 0.f, S = 0.f, Q = 0.f;
#pragma unroll
    for (int h = 0; h < HP; ++h) {
        float z = 0.f;
#pragma unroll
        for (int k = 0; k < T_IN; ++k) z = fmaf(sw[h * T_IN + k], fr[k], z);
        P = fmaf(z, sgw[h], P);
        R = fmaf(z, sgw[HP + h], R);
        S += z;
        Q = fmaf(z, z, Q);
    }
    g_node[t] = make_float4(P, R, S, Q);
}

// ---------------- velocity branch: 12 -> 32 -> LN -> relu -> 1 -> sigmoid ----------------
__device__ __forceinline__ float vbranch(const float (&in)[T_IN],
                                         const float* __restrict__ w1,
                                         const float* __restrict__ b1,
                                         const float* __restrict__ lg,
                                         const float* __restrict__ lb,
                                         const float* __restrict__ w2,
                                         float b2) {
    float h[HV];
    float mean = 0.f;
#pragma unroll
    for (int j = 0; j < HV; ++j) {
        float z = b1[j];
#pragma unroll
        for (int k = 0; k < T_IN; ++k) z = fmaf(w1[j * T_IN + k], in[k], z);
        h[j] = z;
        mean += z;
    }
    mean *= (1.0f / HV);
    float var = 0.f;
#pragma unroll
    for (int j = 0; j < HV; ++j) { float d = h[j] - mean; var = fmaf(d, d, var); }
    var *= (1.0f / HV);
    float inv = rsqrtf(var + 1e-5f);
    float s = b2;
#pragma unroll
    for (int j = 0; j < HV; ++j) {
        float y = fmaf((h[j] - mean) * inv, lg[j], lb[j]);
        y = fmaxf(y, 0.f);
        s = fmaf(y, w2[j], s);
    }
    return 1.0f / (1.0f + expf(-s));
}

// ---------------- edge pass 1 (heavy) ----------------
struct EP {
    const float *up, *dn, *dist, *alpha, *feat;
    const int   *src, *dst;
    const float *l11w, *l11b, *ln11g, *ln11b, *l12w, *l12b;
    const float *l21w, *l21b, *ln21g, *ln21b, *l22w, *l22b;
    const float *l3w, *l3b;
};

__global__ __launch_bounds__(256)
void edge1_kernel(EP p) {
    __shared__ float sm[1033];
    int tid = threadIdx.x;
    for (int i = tid; i < 384; i += 256) { sm[i] = p.l11w[i]; sm[512 + i] = p.l21w[i]; }
    if (tid < 32) {
        sm[384 + tid] = p.l11b[tid];  sm[416 + tid] = p.ln11g[tid];
        sm[448 + tid] = p.ln11b[tid]; sm[480 + tid] = p.l12w[tid];
        sm[896 + tid] = p.l21b[tid];  sm[928 + tid] = p.ln21g[tid];
        sm[960 + tid] = p.ln21b[tid]; sm[992 + tid] = p.l22w[tid];
    }
    if (tid == 0) {
        sm[1024] = p.l12b[0]; sm[1025] = p.l22b[0];
        sm[1026] = p.l3w[0];  sm[1027] = p.l3w[1]; sm[1028] = p.l3w[2];
        sm[1029] = p.l3b[0];
        sm[1030] = g_gw[128]; sm[1031] = g_GC[0];  sm[1032] = g_GC[1];
    }
    __syncthreads();

    int t = blockIdx.x * 256 + tid;
    if (t >= EB) return;
    int e = t >> 3;
    int b = t & 7;

    float in[T_IN];
    // upstream branch
    {
        const float4* u4 = reinterpret_cast<const float4*>(p.up) + (size_t)t * 3;
        float4 a0 = u4[0], a1 = u4[1], a2 = u4[2];
        in[0]=a0.x; in[1]=a0.y; in[2]=a0.z;  in[3]=a0.w;
        in[4]=a1.x; in[5]=a1.y; in[6]=a1.z;  in[7]=a1.w;
        in[8]=a2.x; in[9]=a2.y; in[10]=a2.z; in[11]=a2.w;
    }
    float xup = vbranch(in, sm + 0, sm + 384, sm + 416, sm + 448, sm + 480, sm[1024]);
    // downstream branch (reuse regs)
    {
        const float4* u4 = reinterpret_cast<const float4*>(p.dn) + (size_t)t * 3;
        float4 a0 = u4[0], a1 = u4[1], a2 = u4[2];
        in[0]=a0.x; in[1]=a0.y; in[2]=a0.z;  in[3]=a0.w;
        in[4]=a1.x; in[5]=a1.y; in[6]=a1.z;  in[7]=a1.w;
        in[8]=a2.x; in[9]=a2.y; in[10]=a2.z; in[11]=a2.w;
    }
    float xdn = vbranch(in, sm + 512, sm + 896, sm + 928, sm + 960, sm + 992, sm[1025]);

    float al = p.alpha[e];
    float xv = sm[1026] * xup + sm[1027] * xdn + sm[1028] * al + sm[1029];
    // softplus (stable), clamp to 3
    float v  = (xv > 0.f) ? (xv + log1pf(expf(-xv))) : log1pf(expf(xv));
    v = fminf(v, 3.0f);
    float Tt = p.dist[e] / (v + 1e-5f);

    float Tidx = fminf(fmaxf(rintf(Tt / 10.0f), 0.0f), 11.0f); // round-half-even
    int   n    = T_IN - (int)Tidx;                              // 1..12
    float alc  = fminf(fmaxf(al, 0.f), 1.f);
    float F    = 1.0f / (1.0f + alc * Tt);
    float omF  = 1.0f - F;

    int se = p.src[e];
    int de = p.dst[e];

    // diffusion dot with gathered feature[src]
    float f[T_IN];
    {
        const float4* f4 = reinterpret_cast<const float4*>(p.feat)
                           + ((size_t)se * B + b) * 3;
        float4 a0 = f4[0], a1 = f4[1], a2 = f4[2];
        f[0]=a0.x; f[1]=a0.y; f[2]=a0.z;  f[3]=a0.w;
        f[4]=a1.x; f[5]=a1.y; f[6]=a1.z;  f[7]=a1.w;
        f[8]=a2.x; f[9]=a2.y; f[10]=a2.z; f[11]=a2.w;
    }
    float acc = 0.f, pw = 0.f;
#pragma unroll
    for (int k = T_IN - 1; k >= 0; --k) {
        if (k == n - 1) pw = F;             // exponent 0 term
        if (k <= n - 1) { acc = fmaf(pw, f[k], acc); pw *= omF; }
    }

    // attention score from folded node stats
    float4 ns = g_node[se * B + b];
    float4 nd = g_node[de * B + b];
    float Ssum = ns.z + nd.z + Tt;
    float m    = Ssum * (1.0f / 129.0f);
    float q    = ns.w + nd.w + Tt * Tt;
    float var  = q * (1.0f / 129.0f) - m * m;
    float dot  = ns.x + nd.y + Tt * sm[1030];
    float a    = (dot - m * sm[1031]) * rsqrtf(var + 1e-5f) + sm[1032];
    a = (a >= 0.f) ? a : 0.01f * a;         // leaky_relu(0.01)

    g_att[t]  = a;
    g_dsum[t] = acc;
    atomicMax(&g_amax[se * B + b], f2ord(a));
}

// ---------------- edge pass 2: ex = exp(a - amax[src]); den[src] += ex ----------------
__global__ __launch_bounds__(256)
void edge2_kernel(const int* __restrict__ src) {
    int t = blockIdx.x * 256 + threadIdx.x;
    if (t >= EB) return;
    int e = t >> 3, b = t & 7;
    int se = src[e];
    float amax = ord2f(g_amax[se * B + b]);
    float ex = expf(g_att[t] - amax);
    g_att[t] = ex;
    atomicAdd(&g_den[se * B + b], ex);
}

// ---------------- edge pass 3: pred[dst] += ex/den[src] * dsum ----------------
__global__ __launch_bounds__(256)
void edge3_kernel(const int* __restrict__ src, const int* __restrict__ dst,
                  float* __restrict__ out) {
    int t = blockIdx.x * 256 + threadIdx.x;
    if (t >= EB) return;
    int e = t >> 3, b = t & 7;
    int se = src[e];
    int de = dst[e];
    float val = (g_att[t] / g_den[se * B + b]) * g_dsum[t];
    atomicAdd(&out[de * B + b], val);
}

// ---------------- launch ----------------
extern "C" void kernel_launch(void* const* d_in, const int* in_sizes, int n_in,
                              void* d_out, int out_size) {
    // Order disambiguation:
    //   setup_inputs dict order: [feature, up, dn, dist, src, dst, alpha, fc_w, ...]
    //   reference signature order: [feature, up, dn, dist, alpha, fc_w(768), ... , src, dst]
    bool sig_order = (n_in >= 6 && in_sizes[5] == HP * T_IN);   // fc_w=768 at idx 5

    int i_feat = 0, i_up = 1, i_dn = 2, i_dist = 3;
    int i_src, i_dst, i_alpha, i_fcw, i_ln2g, i_ln2b, i_attnw;
    int i_l11w, i_l11b, i_ln11g, i_ln11b, i_l12w, i_l12b;
    int i_l21w, i_l21b, i_ln21g, i_ln21b, i_l22w, i_l22b, i_l3w, i_l3b;

    if (!sig_order) {
        i_src = 4;  i_dst = 5;  i_alpha = 6;  i_fcw = 7;
        i_ln2g = 8; i_ln2b = 9; i_attnw = 10;
        i_l11w = 11; i_l11b = 12; i_ln11g = 13; i_ln11b = 14; i_l12w = 15; i_l12b = 16;
        i_l21w = 17; i_l21b = 18; i_ln21g = 19; i_ln21b = 20; i_l22w = 21; i_l22b = 22;
        i_l3w = 23;  i_l3b = 24;
    } else {
        i_alpha = 4; i_fcw = 5;
        i_ln2g = 6;  i_ln2b = 7; i_attnw = 8;
        i_l11w = 9;  i_l11b = 10; i_ln11g = 11; i_ln11b = 12; i_l12w = 13; i_l12b = 14;
        i_l21w = 15; i_l21b = 16; i_ln21g = 17; i_ln21b = 18; i_l22w = 19; i_l22b = 20;
        i_l3w = 21;  i_l3b = 22;  i_src = 23;   i_dst = 24;
    }

    const float* feat  = (const float*)d_in[i_feat];
    const float* up    = (const float*)d_in[i_up];
    const float* dn    = (const float*)d_in[i_dn];
    const float* dist  = (const float*)d_in[i_dist];
    const float* alpha = (const float*)d_in[i_alpha];
    const int*   src   = (const int*)d_in[i_src];
    const int*   dst   = (const int*)d_in[i_dst];

    float* out = (float*)d_out;

    prep_kernel<<<1, 256>>>((const float*)d_in[i_ln2g],
                            (const float*)d_in[i_ln2b],
                            (const float*)d_in[i_attnw]);

    init_kernel<<<(NB + 255) / 256, 256>>>(out);

    node_kernel<<<NB / 128, 128>>>(feat, (const float*)d_in[i_fcw]);

    EP p;
    p.up = up; p.dn = dn; p.dist = dist; p.alpha = alpha; p.feat = feat;
    p.src = src; p.dst = dst;
    p.l11w  = (const float*)d_in[i_l11w];  p.l11b  = (const float*)d_in[i_l11b];
    p.ln11g = (const float*)d_in[i_ln11g]; p.ln11b = (const float*)d_in[i_ln11b];
    p.l12w  = (const float*)d_in[i_l12w];  p.l12b  = (const float*)d_in[i_l12b];
    p.l21w  = (const float*)d_in[i_l21w];  p.l21b  = (const float*)d_in[i_l21b];
    p.ln21g = (const float*)d_in[i_ln21g]; p.ln21b = (const float*)d_in[i_ln21b];
    p.l22w  = (const float*)d_in[i_l22w];  p.l22b  = (const float*)d_in[i_l22b];
    p.l3w   = (const float*)d_in[i_l3w];   p.l3b   = (const float*)d_in[i_l3b];

    edge1_kernel<<<EB / 256, 256>>>(p);
    edge2_kernel<<<EB / 256, 256>>>(src);
    edge3_kernel<<<EB / 256, 256>>>(src, dst, out);
}